// round 13
// baseline (speedup 1.0000x reference)
#include <cuda_runtime.h>
#include <cuda_fp16.h>
#include <cstdint>
#include <math.h>

#define Bb 8
#define Tt 64
#define Nn 128
#define Dd 512
#define KHh 8
#define DHh 64
#define KSz 3
#define EPSv 1e-5f

#define NELEM (Bb*Tt*Nn*Dd)   // 16,777,216

// weight prescale (keeps fp16 weights away from subnormals)
#define WSCALE 1024.0f
#define WISCALE 0.0009765625f

// ======================= device scratch =======================
static __device__ __half g_Qh[NELEM];
static __device__ __half g_Kh[NELEM];
static __device__ __half g_Vh[NELEM];
static __device__ __half g_Xh[NELEM];
static __device__ __half g_AOh[NELEM];
static __device__ __half g_wqh[KSz*Dd*Dd];
static __device__ __half g_wkh[KSz*Dd*Dd];
static __device__ __half g_wvh[Dd*Dd];
static __device__ __half g_woh[Dd*Dd];
static __device__ float g_qsc[Dd], g_qsh[Dd];
static __device__ float g_ksc[Dd], g_ksh[Dd];

// ======================= helpers =======================
__device__ __forceinline__ uint32_t smem_u32(const void* p) {
    uint32_t a;
    asm("{ .reg .u64 t; cvta.to.shared.u64 t, %1; cvt.u32.u64 %0, t; }" : "=r"(a) : "l"(p));
    return a;
}
__device__ __forceinline__ uint32_t lds32(uint32_t a) {
    uint32_t v;
    asm volatile("ld.shared.b32 %0, [%1];" : "=r"(v) : "r"(a));
    return v;
}
__device__ __forceinline__ void cpasync16(uint32_t dst, const void* src) {
    asm volatile("cp.async.cg.shared.global [%0], [%1], 16;" :: "r"(dst), "l"(src));
}
#define CP_COMMIT() asm volatile("cp.async.commit_group;" ::: "memory")
#define CP_WAIT1()  asm volatile("cp.async.wait_group 1;" ::: "memory")

__device__ __forceinline__ void mma16816h(float* c, const uint32_t* a, uint32_t b0, uint32_t b1) {
    asm volatile(
        "mma.sync.aligned.m16n8k16.row.col.f32.f16.f16.f32 "
        "{%0,%1,%2,%3}, {%4,%5,%6,%7}, {%8,%9}, {%0,%1,%2,%3};"
        : "+f"(c[0]), "+f"(c[1]), "+f"(c[2]), "+f"(c[3])
        : "r"(a[0]), "r"(a[1]), "r"(a[2]), "r"(a[3]), "r"(b0), "r"(b1));
}
#define LDMX4(r, addr) \
    asm volatile("ldmatrix.sync.aligned.m8n8.x4.shared.b16 {%0,%1,%2,%3}, [%4];" \
        : "=r"((r)[0]), "=r"((r)[1]), "=r"((r)[2]), "=r"((r)[3]) : "r"(addr))
#define LDMX4T(r, addr) \
    asm volatile("ldmatrix.sync.aligned.m8n8.x4.trans.shared.b16 {%0,%1,%2,%3}, [%4];" \
        : "=r"((r)[0]), "=r"((r)[1]), "=r"((r)[2]), "=r"((r)[3]) : "r"(addr))

__device__ __forceinline__ uint32_t packh2(float a, float b) {
    __half2 h = __floats2half2_rn(a, b);
    return *(const uint32_t*)&h;
}

// ======================= prep kernels (R12-proven set) =======================
__global__ void to_fp16(const float* __restrict__ x, __half* __restrict__ y, int n)
{
    int i = (blockIdx.x * blockDim.x + threadIdx.x) * 4;
    if (i >= n) return;
    float4 v = *(const float4*)(x + i);
    uint2 o;
    o.x = packh2(v.x, v.y);
    o.y = packh2(v.z, v.w);
    *(uint2*)(y + i) = o;
}

__global__ void to_fp16_ws2(const float* __restrict__ x0, __half* __restrict__ y0,
                            const float* __restrict__ x1, __half* __restrict__ y1, int n)
{
    int i = (blockIdx.x * blockDim.x + threadIdx.x) * 4;
    if (i >= n) return;
    float4 v = *(const float4*)(x0 + i);
    uint2 o;
    o.x = packh2(v.x * WSCALE, v.y * WSCALE);
    o.y = packh2(v.z * WSCALE, v.w * WSCALE);
    *(uint2*)(y0 + i) = o;
    v = *(const float4*)(x1 + i);
    o.x = packh2(v.x * WSCALE, v.y * WSCALE);
    o.y = packh2(v.z * WSCALE, v.w * WSCALE);
    *(uint2*)(y1 + i) = o;
}

__global__ void repack_conv2(const float* __restrict__ Wq, __half* __restrict__ oq,
                             const float* __restrict__ Wk, __half* __restrict__ ok)
{
    int idx = blockIdx.x * blockDim.x + threadIdx.x;
    if (idx >= KSz * Dd * Dd) return;
    int s = idx / (Dd * Dd);
    int r = idx - s * Dd * Dd;
    oq[idx] = __float2half_rn(Wq[(size_t)r * KSz + s] * WSCALE);
    ok[idx] = __float2half_rn(Wk[(size_t)r * KSz + s] * WSCALE);
}

__global__ void affine_k2(const float* __restrict__ bq, const float* __restrict__ gq,
                          const float* __restrict__ betaq, const float* __restrict__ mq,
                          const float* __restrict__ vq,
                          const float* __restrict__ bk, const float* __restrict__ gk,
                          const float* __restrict__ betak, const float* __restrict__ mk,
                          const float* __restrict__ vk,
                          float* __restrict__ qsc, float* __restrict__ qsh,
                          float* __restrict__ ksc, float* __restrict__ ksh) {
    int e = blockIdx.x * blockDim.x + threadIdx.x;
    if (e >= Dd) return;
    float sq = gq[e] * rsqrtf(vq[e] + EPSv);
    qsc[e] = sq;
    qsh[e] = betaq[e] + (bq[e] - mq[e]) * sq;
    float sk = gk[e] * rsqrtf(vk[e] + EPSv);
    ksc[e] = sk;
    ksh[e] = betak[e] + (bk[e] - mk[e]) * sk;
}

// ======================= GEMM common =======================
#define TILE_B  (128 * 80)            // 10240 B per fp16 tile (K=32 chunk)

// ---------- fused Q+K conv GEMM (proven) ----------
#define QK_STAGE_B (3 * TILE_B)       // A, Bq, Bk
#define SMEM_QK (3 * QK_STAGE_B)      // 92160

struct StageSrcQK { const __half *a, *bq, *bk; };

__device__ __forceinline__ void issue_stage_qk(uint32_t sbuf, const StageSrcQK& s, int tid) {
#pragma unroll
    for (int j = 0; j < 2; ++j) {
        const int idx = tid + 256 * j;
        const int r   = idx >> 2;
        const int c16 = idx & 3;
        const uint32_t doff = (uint32_t)(r * 80 + c16 * 16);
        const size_t  goff = (size_t)r * Dd + c16 * 8;
        cpasync16(sbuf +              doff, s.a  + goff);
        cpasync16(sbuf +     TILE_B + doff, s.bq + goff);
        cpasync16(sbuf + 2 * TILE_B + doff, s.bk + goff);
    }
}

__global__ void __launch_bounds__(256)
mma_gemm_qk(const __half* __restrict__ A,
            const __half* __restrict__ Bq, const __half* __restrict__ Bk,
            const float* __restrict__ qsc, const float* __restrict__ qsh,
            const float* __restrict__ ksc, const float* __restrict__ ksh,
            __half* __restrict__ OutQ, __half* __restrict__ OutK)
{
    extern __shared__ __align__(16) char sm[];
    const uint32_t base_u = smem_u32(sm);

    const int tid = threadIdx.x;
    const int wid = tid >> 5;
    const int lane = tid & 31;
    const int qr = lane >> 2;
    const int qc = lane & 3;

    const int warp_m = (wid & 3) * 32;
    const int warp_n = (wid >> 2) * 64;

    const int e0 = blockIdx.x * 128;
    const int bt = blockIdx.y;
    const int t  = bt & (Tt - 1);

    int taps[KSz]; int ntv = 0;
    for (int s = 0; s < KSz; ++s)
        if (t - (KSz - 1) + s >= 0) taps[ntv++] = s;
    const int ns = ntv * 16;

    auto src_of = [&](int c) -> StageSrcQK {
        const int s  = taps[c >> 4];
        const int k0 = (c & 15) * 32;
        const size_t arow = (size_t)(bt - (KSz - 1) + s) * 128;
        const size_t boff = (size_t)s * Dd * Dd + (size_t)e0 * Dd + k0;
        StageSrcQK r;
        r.a  = A + arow * Dd + k0;
        r.bq = Bq + boff;
        r.bk = Bk + boff;
        return r;
    };

    float accq[2][8][4], acck[2][8][4];
#pragma unroll
    for (int i = 0; i < 2; ++i)
#pragma unroll
        for (int j = 0; j < 8; ++j)
#pragma unroll
            for (int q = 0; q < 4; ++q) { accq[i][j][q] = 0.0f; acck[i][j][q] = 0.0f; }

    issue_stage_qk(base_u, src_of(0), tid); CP_COMMIT();
    if (ns > 1) issue_stage_qk(base_u + QK_STAGE_B, src_of(1), tid);
    CP_COMMIT();

    const uint32_t a_base0 = (uint32_t)((warp_m + qr) * 80 + qc * 4);
    const uint32_t b_base0 = (uint32_t)((warp_n + qr) * 80 + qc * 4);

    int buf = 0;
    for (int c = 0; c < ns; ++c) {
        CP_WAIT1();
        __syncthreads();

        int buf2 = buf + 2; if (buf2 >= 3) buf2 -= 3;
        if (c + 2 < ns) issue_stage_qk(base_u + (uint32_t)buf2 * QK_STAGE_B, src_of(c + 2), tid);
        CP_COMMIT();

        const uint32_t sbuf = base_u + (uint32_t)buf * QK_STAGE_B;
        const uint32_t Ab = sbuf, Bqs = sbuf + TILE_B, Bks = sbuf + 2 * TILE_B;

#pragma unroll
        for (int kk = 0; kk < 2; ++kk) {
            const uint32_t kb = (uint32_t)(kk * 32);
            uint32_t ah[2][4];
#pragma unroll
            for (int mt = 0; mt < 2; ++mt) {
                const uint32_t ra = a_base0 + (uint32_t)(mt * 16 * 80) + kb;
                ah[mt][0] = lds32(Ab + ra);
                ah[mt][1] = lds32(Ab + ra + 8 * 80);
                ah[mt][2] = lds32(Ab + ra + 16);
                ah[mt][3] = lds32(Ab + ra + 8 * 80 + 16);
            }
#pragma unroll
            for (int nt = 0; nt < 8; ++nt) {
                const uint32_t rb = b_base0 + (uint32_t)(nt * 8 * 80) + kb;
                const uint32_t q0 = lds32(Bqs + rb);
                const uint32_t q1 = lds32(Bqs + rb + 16);
                const uint32_t k0r = lds32(Bks + rb);
                const uint32_t k1r = lds32(Bks + rb + 16);
#pragma unroll
                for (int mt = 0; mt < 2; ++mt) {
                    mma16816h(accq[mt][nt], ah[mt], q0, q1);
                    mma16816h(acck[mt][nt], ah[mt], k0r, k1r);
                }
            }
        }
        if (++buf >= 3) buf -= 3;
    }

#pragma unroll
    for (int mt = 0; mt < 2; ++mt) {
#pragma unroll
        for (int nt = 0; nt < 8; ++nt) {
            const int col = warp_n + nt * 8 + 2 * qc;
            const int e   = e0 + col;
            const float qs0 = qsc[e] * WISCALE,     qs1 = qsc[e + 1] * WISCALE;
            const float qh0 = qsh[e],               qh1 = qsh[e + 1];
            const float ks0 = ksc[e] * WISCALE,     ks1 = ksc[e + 1] * WISCALE;
            const float kh0 = ksh[e],               kh1 = ksh[e + 1];
            const int row0 = warp_m + mt * 16 + qr;
            const size_t o0 = ((size_t)bt * 128 + row0) * Dd + e;
            const size_t o1 = ((size_t)bt * 128 + row0 + 8) * Dd + e;
            *(uint32_t*)(OutQ + o0) = packh2(accq[mt][nt][0] * qs0 + qh0, accq[mt][nt][1] * qs1 + qh1);
            *(uint32_t*)(OutQ + o1) = packh2(accq[mt][nt][2] * qs0 + qh0, accq[mt][nt][3] * qs1 + qh1);
            *(uint32_t*)(OutK + o0) = packh2(acck[mt][nt][0] * ks0 + kh0, acck[mt][nt][1] * ks1 + kh1);
            *(uint32_t*)(OutK + o1) = packh2(acck[mt][nt][2] * ks0 + kh0, acck[mt][nt][3] * ks1 + kh1);
        }
    }
}

// ---------- single-B GEMM (V projection / O projection) ----------
#define ONE_STAGE_B (2 * TILE_B)
#define SMEM_ONE (3 * ONE_STAGE_B)    // 61440

struct StageSrc1 { const __half *a, *b; };

__device__ __forceinline__ void issue_stage1(uint32_t sbuf, const StageSrc1& s, int tid) {
#pragma unroll
    for (int j = 0; j < 2; ++j) {
        const int idx = tid + 256 * j;
        const int r   = idx >> 2;
        const int c16 = idx & 3;
        const uint32_t doff = (uint32_t)(r * 80 + c16 * 16);
        const size_t  goff = (size_t)r * Dd + c16 * 8;
        cpasync16(sbuf +          doff, s.a + goff);
        cpasync16(sbuf + TILE_B + doff, s.b + goff);
    }
}

__global__ void __launch_bounds__(256, 2)
mma_gemm_one(const __half* __restrict__ A, const __half* __restrict__ B,
             const float* __restrict__ shift,
             float* __restrict__ OutF, __half* __restrict__ OutH)
{
    extern __shared__ __align__(16) char sm[];
    const uint32_t base_u = smem_u32(sm);

    const int tid = threadIdx.x;
    const int wid = tid >> 5;
    const int lane = tid & 31;
    const int qr = lane >> 2;
    const int qc = lane & 3;

    const int warp_m = (wid & 3) * 32;
    const int warp_n = (wid >> 2) * 64;

    const int e0 = blockIdx.x * 128;
    const int bt = blockIdx.y;
    const int ns = 16;

    auto src_of = [&](int c) -> StageSrc1 {
        const int k0 = c * 32;
        StageSrc1 r;
        r.a = A + (size_t)bt * 128 * Dd + k0;
        r.b = B + (size_t)e0 * Dd + k0;
        return r;
    };

    float acc[2][8][4];
#pragma unroll
    for (int i = 0; i < 2; ++i)
#pragma unroll
        for (int j = 0; j < 8; ++j)
#pragma unroll
            for (int q = 0; q < 4; ++q) acc[i][j][q] = 0.0f;

    issue_stage1(base_u, src_of(0), tid); CP_COMMIT();
    issue_stage1(base_u + ONE_STAGE_B, src_of(1), tid);
    CP_COMMIT();

    const uint32_t a_base0 = (uint32_t)((warp_m + qr) * 80 + qc * 4);
    const uint32_t b_base0 = (uint32_t)((warp_n + qr) * 80 + qc * 4);

    int buf = 0;
    for (int c = 0; c < ns; ++c) {
        CP_WAIT1();
        __syncthreads();

        int buf2 = buf + 2; if (buf2 >= 3) buf2 -= 3;
        if (c + 2 < ns) issue_stage1(base_u + (uint32_t)buf2 * ONE_STAGE_B, src_of(c + 2), tid);
        CP_COMMIT();

        const uint32_t sbuf = base_u + (uint32_t)buf * ONE_STAGE_B;
        const uint32_t Ab = sbuf, Bbs = sbuf + TILE_B;

#pragma unroll
        for (int kk = 0; kk < 2; ++kk) {
            const uint32_t kb = (uint32_t)(kk * 32);
            uint32_t ah[2][4];
#pragma unroll
            for (int mt = 0; mt < 2; ++mt) {
                const uint32_t ra = a_base0 + (uint32_t)(mt * 16 * 80) + kb;
                ah[mt][0] = lds32(Ab + ra);
                ah[mt][1] = lds32(Ab + ra + 8 * 80);
                ah[mt][2] = lds32(Ab + ra + 16);
                ah[mt][3] = lds32(Ab + ra + 8 * 80 + 16);
            }
#pragma unroll
            for (int nt = 0; nt < 8; ++nt) {
                const uint32_t rb = b_base0 + (uint32_t)(nt * 8 * 80) + kb;
                const uint32_t b0 = lds32(Bbs + rb);
                const uint32_t b1 = lds32(Bbs + rb + 16);
#pragma unroll
                for (int mt = 0; mt < 2; ++mt)
                    mma16816h(acc[mt][nt], ah[mt], b0, b1);
            }
        }
        if (++buf >= 3) buf -= 3;
    }

#pragma unroll
    for (int mt = 0; mt < 2; ++mt) {
#pragma unroll
        for (int nt = 0; nt < 8; ++nt) {
            const int col = warp_n + nt * 8 + 2 * qc;
            const int e   = e0 + col;
            const float h0 = shift[e], h1 = shift[e + 1];
            const int row0 = warp_m + mt * 16 + qr;
            const size_t o0 = ((size_t)bt * 128 + row0) * Dd + e;
            const size_t o1 = ((size_t)bt * 128 + row0 + 8) * Dd + e;
            const float v00 = acc[mt][nt][0] * WISCALE + h0;
            const float v01 = acc[mt][nt][1] * WISCALE + h1;
            const float v10 = acc[mt][nt][2] * WISCALE + h0;
            const float v11 = acc[mt][nt][3] * WISCALE + h1;
            if (OutF) {
                *(float2*)(OutF + o0) = make_float2(v00, v01);
                *(float2*)(OutF + o1) = make_float2(v10, v11);
            } else {
                *(uint32_t*)(OutH + o0) = packh2(v00, v01);
                *(uint32_t*)(OutH + o1) = packh2(v10, v11);
            }
        }
    }
}

// ======================= fp16 tensor-core attention (2 heads / block) =======================
// One block per (b, n, head-pair). 8 warps: warps 0-3 -> head 2hp, warps 4-7 -> head 2hp+1.
// Adjacent heads are contiguous in D, so each row load is 256B contiguous.
// Row stride 272B; 272 mod 128 == 144 mod 128 -> identical bank-conflict structure
// to the proven single-head kernel.
#define ATT2_ROW 272
#define ATT2_MAT (64 * ATT2_ROW)       // 17408
#define SMEM_ATT2 (3 * ATT2_MAT)       // 52224

__global__ void __launch_bounds__(256) attn_h16_2(
    const __half* __restrict__ Q, const __half* __restrict__ K,
    const __half* __restrict__ V, __half* __restrict__ O)
{
    extern __shared__ __align__(16) char smd[];
    const uint32_t s_u = smem_u32(smd);
    const uint32_t Qs = s_u, Ks = s_u + ATT2_MAT, Vs = s_u + 2 * ATT2_MAT;

    const int blk = blockIdx.x;
    const int hp = blk & 3;                 // head pair 0..3
    const int n = (blk >> 2) & (Nn - 1);
    const int b = blk >> 9;

    const int tid = threadIdx.x;
    const int wid = tid >> 5;
    const int lane = tid & 31;
    const int hw = wid >> 2;                // head within pair (0/1)
    const int w4 = wid & 3;                 // warp within head group
    const uint32_t headoff = (uint32_t)hw * 128;  // byte offset within row

    const size_t tstride = (size_t)Nn * Dd;
    const size_t base = ((size_t)b * Tt * Nn + n) * Dd + (size_t)hp * 2 * DHh;

    // cooperative load: per matrix 64 rows x 256B = 1024 16B-chunks; 4 per thread
#pragma unroll
    for (int i = 0; i < 4; ++i) {
        const int id = tid + 256 * i;
        const int r = id >> 4, c = id & 15;
        const size_t g = base + (size_t)r * tstride + c * 8;
        const uint32_t d = (uint32_t)(r * ATT2_ROW + c * 16);
        *(uint4*)(smd + d)                = *(const uint4*)(Q + g);
        *(uint4*)(smd + ATT2_MAT + d)     = *(const uint4*)(K + g);
        *(uint4*)(smd + 2 * ATT2_MAT + d) = *(const uint4*)(V + g);
    }
    __syncthreads();

    const int m0 = w4 * 16;

    // ---- S = Q @ K^T ----
    float s[8][4];
#pragma unroll
    for (int j = 0; j < 8; ++j)
#pragma unroll
        for (int q = 0; q < 4; ++q) s[j][q] = 0.0f;

#pragma unroll
    for (int ks = 0; ks < 4; ++ks) {
        const int k0 = ks * 16;
        uint32_t a[4];
        LDMX4(a, Qs + headoff + (uint32_t)((m0 + (lane & 15)) * ATT2_ROW + 2 * k0 + (lane >> 4) * 16));
#pragma unroll
        for (int jp = 0; jp < 4; ++jp) {
            const int p0 = jp * 16;
            uint32_t kb[4];
            const int row = p0 + (lane & 7) + ((lane & 16) ? 8 : 0);
            const int colb = 2 * k0 + ((lane & 8) ? 16 : 0);
            LDMX4(kb, Ks + headoff + (uint32_t)(row * ATT2_ROW + colb));
            mma16816h(s[2 * jp],     a, kb[0], kb[1]);
            mma16816h(s[2 * jp + 1], a, kb[2], kb[3]);
        }
    }

    // ---- softmax ----
    float mx0 = -1e30f, mx1 = -1e30f;
#pragma unroll
    for (int j = 0; j < 8; ++j) {
#pragma unroll
        for (int q = 0; q < 4; ++q) s[j][q] *= 0.125f;
        mx0 = fmaxf(mx0, fmaxf(s[j][0], s[j][1]));
        mx1 = fmaxf(mx1, fmaxf(s[j][2], s[j][3]));
    }
    mx0 = fmaxf(mx0, __shfl_xor_sync(0xffffffffu, mx0, 1));
    mx0 = fmaxf(mx0, __shfl_xor_sync(0xffffffffu, mx0, 2));
    mx1 = fmaxf(mx1, __shfl_xor_sync(0xffffffffu, mx1, 1));
    mx1 = fmaxf(mx1, __shfl_xor_sync(0xffffffffu, mx1, 2));

    float sum0 = 0.0f, sum1 = 0.0f;
#pragma unroll
    for (int j = 0; j < 8; ++j) {
        s[j][0] = __expf(s[j][0] - mx0);
        s[j][1] = __expf(s[j][1] - mx0);
        s[j][2] = __expf(s[j][2] - mx1);
        s[j][3] = __expf(s[j][3] - mx1);
        sum0 += s[j][0] + s[j][1];
        sum1 += s[j][2] + s[j][3];
    }
    sum0 += __shfl_xor_sync(0xffffffffu, sum0, 1);
    sum0 += __shfl_xor_sync(0xffffffffu, sum0, 2);
    sum1 += __shfl_xor_sync(0xffffffffu, sum1, 1);
    sum1 += __shfl_xor_sync(0xffffffffu, sum1, 2);
    const float inv0 = 1.0f / sum0;
    const float inv1 = 1.0f / sum1;

    // ---- O = P @ V ----
    float o[8][4];
#pragma unroll
    for (int j = 0; j < 8; ++j)
#pragma unroll
        for (int q = 0; q < 4; ++q) o[j][q] = 0.0f;

#pragma unroll
    for (int kk = 0; kk < 4; ++kk) {
        uint32_t a[4];
        a[0] = packh2(s[2 * kk][0] * inv0,     s[2 * kk][1] * inv0);
        a[1] = packh2(s[2 * kk][2] * inv1,     s[2 * kk][3] * inv1);
        a[2] = packh2(s[2 * kk + 1][0] * inv0, s[2 * kk + 1][1] * inv0);
        a[3] = packh2(s[2 * kk + 1][2] * inv1, s[2 * kk + 1][3] * inv1);
#pragma unroll
        for (int dp = 0; dp < 4; ++dp) {
            uint32_t vb[4];
            const int row = kk * 16 + (lane & 7) + ((lane & 8) ? 8 : 0);
            const int colb = dp * 32 + ((lane & 16) ? 16 : 0);
            LDMX4T(vb, Vs + headoff + (uint32_t)(row * ATT2_ROW + colb));
            mma16816h(o[2 * dp],     a, vb[0], vb[1]);
            mma16816h(o[2 * dp + 1], a, vb[2], vb[3]);
        }
    }

    // ---- store O (fp16) ----
    const int g0 = m0 + (lane >> 2);
    const size_t obase = base + (size_t)hw * DHh;
#pragma unroll
    for (int dt = 0; dt < 8; ++dt) {
        const int col = dt * 8 + 2 * (lane & 3);
        *(uint32_t*)(O + obase + (size_t)g0 * tstride + col)       = packh2(o[dt][0], o[dt][1]);
        *(uint32_t*)(O + obase + (size_t)(g0 + 8) * tstride + col) = packh2(o[dt][2], o[dt][3]);
    }
}

// ======================= launch =======================
extern "C" void kernel_launch(void* const* d_in, const int* in_sizes, int n_in,
                              void* d_out, int out_size)
{
    const float* X     = (const float*)d_in[0];
    const float* Wq    = (const float*)d_in[1];
    const float* bq    = (const float*)d_in[2];
    const float* gq    = (const float*)d_in[3];
    const float* betaq = (const float*)d_in[4];
    const float* mq    = (const float*)d_in[5];
    const float* vq    = (const float*)d_in[6];
    const float* Wk    = (const float*)d_in[7];
    const float* bk    = (const float*)d_in[8];
    const float* gk    = (const float*)d_in[9];
    const float* betak = (const float*)d_in[10];
    const float* mk    = (const float*)d_in[11];
    const float* vk    = (const float*)d_in[12];
    const float* Wv    = (const float*)d_in[13];
    const float* bv    = (const float*)d_in[14];
    const float* Wo    = (const float*)d_in[15];
    const float* bo    = (const float*)d_in[16];
    float* out = (float*)d_out;

    float *pqsc, *pqsh, *pksc, *pksh;
    __half *pQh, *pKh, *pVh, *pXh, *pAOh, *pwqh, *pwkh, *pwvh, *pwoh;
    cudaGetSymbolAddress((void**)&pQh, g_Qh);
    cudaGetSymbolAddress((void**)&pKh, g_Kh);
    cudaGetSymbolAddress((void**)&pVh, g_Vh);
    cudaGetSymbolAddress((void**)&pXh, g_Xh);
    cudaGetSymbolAddress((void**)&pAOh, g_AOh);
    cudaGetSymbolAddress((void**)&pwqh, g_wqh);
    cudaGetSymbolAddress((void**)&pwkh, g_wkh);
    cudaGetSymbolAddress((void**)&pwvh, g_wvh);
    cudaGetSymbolAddress((void**)&pwoh, g_woh);
    cudaGetSymbolAddress((void**)&pqsc, g_qsc);
    cudaGetSymbolAddress((void**)&pqsh, g_qsh);
    cudaGetSymbolAddress((void**)&pksc, g_ksc);
    cudaGetSymbolAddress((void**)&pksh, g_ksh);

    cudaFuncSetAttribute(mma_gemm_qk,  cudaFuncAttributeMaxDynamicSharedMemorySize, SMEM_QK);
    cudaFuncSetAttribute(mma_gemm_one, cudaFuncAttributeMaxDynamicSharedMemorySize, SMEM_ONE);
    cudaFuncSetAttribute(attn_h16_2,   cudaFuncAttributeMaxDynamicSharedMemorySize, SMEM_ATT2);

    // prep (proven merged set: 4 launches)
    to_fp16<<<NELEM/4/256, 256>>>(X, pXh, NELEM);
    repack_conv2<<<(KSz*Dd*Dd + 255)/256, 256>>>(Wq, pwqh, Wk, pwkh);
    to_fp16_ws2<<<(Dd*Dd)/4/256, 256>>>(Wv, pwvh, Wo, pwoh, Dd*Dd);
    affine_k2<<<2, 256>>>(bq, gq, betaq, mq, vq, bk, gk, betak, mk, vk,
                          pqsc, pqsh, pksc, pksh);

    dim3 grid(Dd/128, Bb*Tt);
    // fused Q+K conv GEMM -> fp16
    mma_gemm_qk<<<grid, 256, SMEM_QK>>>(pXh, pwqh, pwkh, pqsc, pqsh, pksc, pksh, pQh, pKh);
    // V projection -> fp16
    mma_gemm_one<<<grid, 256, SMEM_ONE>>>(pXh, pwvh, bv, nullptr, pVh);

    // tensor-core attention (2 heads/block) -> fp16 AO
    attn_h16_2<<<Bb*Nn*4, 256, SMEM_ATT2>>>(pQh, pKh, pVh, pAOh);

    // output projection -> fp32
    mma_gemm_one<<<grid, 256, SMEM_ONE>>>(pAOh, pwoh, bo, out, nullptr);
}

// round 17
// speedup vs baseline: 1.0130x; 1.0130x over previous
#include <cuda_runtime.h>
#include <cuda_fp16.h>
#include <cstdint>
#include <math.h>

#define Bb 8
#define Tt 64
#define Nn 128
#define Dd 512
#define KHh 8
#define DHh 64
#define KSz 3
#define EPSv 1e-5f

#define NELEM (Bb*Tt*Nn*Dd)   // 16,777,216

// weight prescale (keeps fp16 weights away from subnormals)
#define WSCALE 1024.0f
#define WISCALE 0.0009765625f

// ======================= device scratch =======================
static __device__ __half g_Qh[NELEM];
static __device__ __half g_Kh[NELEM];
static __device__ __half g_Vh[NELEM];
static __device__ __half g_Xh[NELEM];
static __device__ __half g_AOh[NELEM];
static __device__ __half g_wqh[KSz*Dd*Dd];
static __device__ __half g_wkh[KSz*Dd*Dd];
static __device__ __half g_wvh[Dd*Dd];
static __device__ __half g_woh[Dd*Dd];
static __device__ float g_qsc[Dd], g_qsh[Dd];
static __device__ float g_ksc[Dd], g_ksh[Dd];

// ======================= helpers =======================
__device__ __forceinline__ uint32_t smem_u32(const void* p) {
    uint32_t a;
    asm("{ .reg .u64 t; cvta.to.shared.u64 t, %1; cvt.u32.u64 %0, t; }" : "=r"(a) : "l"(p));
    return a;
}
__device__ __forceinline__ uint32_t lds32(uint32_t a) {
    uint32_t v;
    asm volatile("ld.shared.b32 %0, [%1];" : "=r"(v) : "r"(a));
    return v;
}
__device__ __forceinline__ void cpasync16(uint32_t dst, const void* src) {
    asm volatile("cp.async.cg.shared.global [%0], [%1], 16;" :: "r"(dst), "l"(src));
}
#define CP_COMMIT() asm volatile("cp.async.commit_group;" ::: "memory")
#define CP_WAIT1()  asm volatile("cp.async.wait_group 1;" ::: "memory")

__device__ __forceinline__ void mma16816h(float* c, const uint32_t* a, uint32_t b0, uint32_t b1) {
    asm volatile(
        "mma.sync.aligned.m16n8k16.row.col.f32.f16.f16.f32 "
        "{%0,%1,%2,%3}, {%4,%5,%6,%7}, {%8,%9}, {%0,%1,%2,%3};"
        : "+f"(c[0]), "+f"(c[1]), "+f"(c[2]), "+f"(c[3])
        : "r"(a[0]), "r"(a[1]), "r"(a[2]), "r"(a[3]), "r"(b0), "r"(b1));
}
#define LDMX4(r, addr) \
    asm volatile("ldmatrix.sync.aligned.m8n8.x4.shared.b16 {%0,%1,%2,%3}, [%4];" \
        : "=r"((r)[0]), "=r"((r)[1]), "=r"((r)[2]), "=r"((r)[3]) : "r"(addr))
#define LDMX4T(r, addr) \
    asm volatile("ldmatrix.sync.aligned.m8n8.x4.trans.shared.b16 {%0,%1,%2,%3}, [%4];" \
        : "=r"((r)[0]), "=r"((r)[1]), "=r"((r)[2]), "=r"((r)[3]) : "r"(addr))

__device__ __forceinline__ uint32_t packh2(float a, float b) {
    __half2 h = __floats2half2_rn(a, b);
    return *(const uint32_t*)&h;
}

// ======================= prep kernels (proven set) =======================
__global__ void to_fp16(const float* __restrict__ x, __half* __restrict__ y, int n)
{
    int i = (blockIdx.x * blockDim.x + threadIdx.x) * 4;
    if (i >= n) return;
    float4 v = *(const float4*)(x + i);
    uint2 o;
    o.x = packh2(v.x, v.y);
    o.y = packh2(v.z, v.w);
    *(uint2*)(y + i) = o;
}

__global__ void to_fp16_ws2(const float* __restrict__ x0, __half* __restrict__ y0,
                            const float* __restrict__ x1, __half* __restrict__ y1, int n)
{
    int i = (blockIdx.x * blockDim.x + threadIdx.x) * 4;
    if (i >= n) return;
    float4 v = *(const float4*)(x0 + i);
    uint2 o;
    o.x = packh2(v.x * WSCALE, v.y * WSCALE);
    o.y = packh2(v.z * WSCALE, v.w * WSCALE);
    *(uint2*)(y0 + i) = o;
    v = *(const float4*)(x1 + i);
    o.x = packh2(v.x * WSCALE, v.y * WSCALE);
    o.y = packh2(v.z * WSCALE, v.w * WSCALE);
    *(uint2*)(y1 + i) = o;
}

__global__ void repack_conv2(const float* __restrict__ Wq, __half* __restrict__ oq,
                             const float* __restrict__ Wk, __half* __restrict__ ok)
{
    int idx = blockIdx.x * blockDim.x + threadIdx.x;
    if (idx >= KSz * Dd * Dd) return;
    int s = idx / (Dd * Dd);
    int r = idx - s * Dd * Dd;
    oq[idx] = __float2half_rn(Wq[(size_t)r * KSz + s] * WSCALE);
    ok[idx] = __float2half_rn(Wk[(size_t)r * KSz + s] * WSCALE);
}

__global__ void affine_k2(const float* __restrict__ bq, const float* __restrict__ gq,
                          const float* __restrict__ betaq, const float* __restrict__ mq,
                          const float* __restrict__ vq,
                          const float* __restrict__ bk, const float* __restrict__ gk,
                          const float* __restrict__ betak, const float* __restrict__ mk,
                          const float* __restrict__ vk,
                          float* __restrict__ qsc, float* __restrict__ qsh,
                          float* __restrict__ ksc, float* __restrict__ ksh) {
    int e = blockIdx.x * blockDim.x + threadIdx.x;
    if (e >= Dd) return;
    float sq = gq[e] * rsqrtf(vq[e] + EPSv);
    qsc[e] = sq;
    qsh[e] = betaq[e] + (bq[e] - mq[e]) * sq;
    float sk = gk[e] * rsqrtf(vk[e] + EPSv);
    ksc[e] = sk;
    ksh[e] = betak[e] + (bk[e] - mk[e]) * sk;
}

// ======================= GEMM common =======================
#define TILE_B  (128 * 80)            // 10240 B per fp16 tile (K=32 chunk)

#define QK_STAGE_B (3 * TILE_B)       // A, Bq, Bk
#define SMEM_QK (3 * QK_STAGE_B)      // 92160
#define ONE_STAGE_B (2 * TILE_B)
#define SMEM_ONE (3 * ONE_STAGE_B)    // 61440

struct StageSrcQK { const __half *a, *bq, *bk; };
struct StageSrc1  { const __half *a, *b; };

__device__ __forceinline__ void issue_stage_qk(uint32_t sbuf, const StageSrcQK& s, int tid) {
#pragma unroll
    for (int j = 0; j < 2; ++j) {
        const int idx = tid + 256 * j;
        const int r   = idx >> 2;
        const int c16 = idx & 3;
        const uint32_t doff = (uint32_t)(r * 80 + c16 * 16);
        const size_t  goff = (size_t)r * Dd + c16 * 8;
        cpasync16(sbuf +              doff, s.a  + goff);
        cpasync16(sbuf +     TILE_B + doff, s.bq + goff);
        cpasync16(sbuf + 2 * TILE_B + doff, s.bk + goff);
    }
}

__device__ __forceinline__ void issue_stage1(uint32_t sbuf, const StageSrc1& s, int tid) {
#pragma unroll
    for (int j = 0; j < 2; ++j) {
        const int idx = tid + 256 * j;
        const int r   = idx >> 2;
        const int c16 = idx & 3;
        const uint32_t doff = (uint32_t)(r * 80 + c16 * 16);
        const size_t  goff = (size_t)r * Dd + c16 * 8;
        cpasync16(sbuf +          doff, s.a + goff);
        cpasync16(sbuf + TILE_B + doff, s.b + goff);
    }
}

// ---------- merged Q+K conv GEMM (z=0) + V projection (z=1) ----------
// z-major CTA ordering schedules all QK CTAs first; V CTAs backfill the QK
// tail wave, removing the inter-kernel drain bubble + launch gap.
__global__ void __launch_bounds__(256)
mma_gemm_qkv(const __half* __restrict__ A,
             const __half* __restrict__ Bq, const __half* __restrict__ Bk,
             const __half* __restrict__ Bv,
             const float* __restrict__ qsc, const float* __restrict__ qsh,
             const float* __restrict__ ksc, const float* __restrict__ ksh,
             const float* __restrict__ vsh,
             __half* __restrict__ OutQ, __half* __restrict__ OutK,
             __half* __restrict__ OutV)
{
    extern __shared__ __align__(16) char sm[];
    const uint32_t base_u = smem_u32(sm);

    const int tid = threadIdx.x;
    const int wid = tid >> 5;
    const int lane = tid & 31;
    const int qr = lane >> 2;
    const int qc = lane & 3;

    const int warp_m = (wid & 3) * 32;
    const int warp_n = (wid >> 2) * 64;

    const int e0 = blockIdx.x * 128;
    const int bt = blockIdx.y;

    const uint32_t a_base0 = (uint32_t)((warp_m + qr) * 80 + qc * 4);
    const uint32_t b_base0 = (uint32_t)((warp_n + qr) * 80 + qc * 4);

    if (blockIdx.z == 1) {
        // ================= V projection path (proven mma_gemm_one body) =================
        const int ns = 16;

        auto src_of = [&](int c) -> StageSrc1 {
            const int k0 = c * 32;
            StageSrc1 r;
            r.a = A + (size_t)bt * 128 * Dd + k0;
            r.b = Bv + (size_t)e0 * Dd + k0;
            return r;
        };

        float acc[2][8][4];
#pragma unroll
        for (int i = 0; i < 2; ++i)
#pragma unroll
            for (int j = 0; j < 8; ++j)
#pragma unroll
                for (int q = 0; q < 4; ++q) acc[i][j][q] = 0.0f;

        issue_stage1(base_u, src_of(0), tid); CP_COMMIT();
        issue_stage1(base_u + ONE_STAGE_B, src_of(1), tid);
        CP_COMMIT();

        int buf = 0;
        for (int c = 0; c < ns; ++c) {
            CP_WAIT1();
            __syncthreads();

            int buf2 = buf + 2; if (buf2 >= 3) buf2 -= 3;
            if (c + 2 < ns) issue_stage1(base_u + (uint32_t)buf2 * ONE_STAGE_B, src_of(c + 2), tid);
            CP_COMMIT();

            const uint32_t sbuf = base_u + (uint32_t)buf * ONE_STAGE_B;
            const uint32_t Ab = sbuf, Bbs = sbuf + TILE_B;

#pragma unroll
            for (int kk = 0; kk < 2; ++kk) {
                const uint32_t kb = (uint32_t)(kk * 32);
                uint32_t ah[2][4];
#pragma unroll
                for (int mt = 0; mt < 2; ++mt) {
                    const uint32_t ra = a_base0 + (uint32_t)(mt * 16 * 80) + kb;
                    ah[mt][0] = lds32(Ab + ra);
                    ah[mt][1] = lds32(Ab + ra + 8 * 80);
                    ah[mt][2] = lds32(Ab + ra + 16);
                    ah[mt][3] = lds32(Ab + ra + 8 * 80 + 16);
                }
#pragma unroll
                for (int nt = 0; nt < 8; ++nt) {
                    const uint32_t rb = b_base0 + (uint32_t)(nt * 8 * 80) + kb;
                    const uint32_t b0 = lds32(Bbs + rb);
                    const uint32_t b1 = lds32(Bbs + rb + 16);
#pragma unroll
                    for (int mt = 0; mt < 2; ++mt)
                        mma16816h(acc[mt][nt], ah[mt], b0, b1);
                }
            }
            if (++buf >= 3) buf -= 3;
        }

#pragma unroll
        for (int mt = 0; mt < 2; ++mt) {
#pragma unroll
            for (int nt = 0; nt < 8; ++nt) {
                const int col = warp_n + nt * 8 + 2 * qc;
                const int e   = e0 + col;
                const float h0 = vsh[e], h1 = vsh[e + 1];
                const int row0 = warp_m + mt * 16 + qr;
                const size_t o0 = ((size_t)bt * 128 + row0) * Dd + e;
                const size_t o1 = ((size_t)bt * 128 + row0 + 8) * Dd + e;
                *(uint32_t*)(OutV + o0) = packh2(acc[mt][nt][0] * WISCALE + h0, acc[mt][nt][1] * WISCALE + h1);
                *(uint32_t*)(OutV + o1) = packh2(acc[mt][nt][2] * WISCALE + h0, acc[mt][nt][3] * WISCALE + h1);
            }
        }
        return;
    }

    // ================= Q+K conv path (proven mma_gemm_qk body) =================
    const int t = bt & (Tt - 1);

    int taps[KSz]; int ntv = 0;
    for (int s = 0; s < KSz; ++s)
        if (t - (KSz - 1) + s >= 0) taps[ntv++] = s;
    const int ns = ntv * 16;

    auto src_of = [&](int c) -> StageSrcQK {
        const int s  = taps[c >> 4];
        const int k0 = (c & 15) * 32;
        const size_t arow = (size_t)(bt - (KSz - 1) + s) * 128;
        const size_t boff = (size_t)s * Dd * Dd + (size_t)e0 * Dd + k0;
        StageSrcQK r;
        r.a  = A + arow * Dd + k0;
        r.bq = Bq + boff;
        r.bk = Bk + boff;
        return r;
    };

    float accq[2][8][4], acck[2][8][4];
#pragma unroll
    for (int i = 0; i < 2; ++i)
#pragma unroll
        for (int j = 0; j < 8; ++j)
#pragma unroll
            for (int q = 0; q < 4; ++q) { accq[i][j][q] = 0.0f; acck[i][j][q] = 0.0f; }

    issue_stage_qk(base_u, src_of(0), tid); CP_COMMIT();
    if (ns > 1) issue_stage_qk(base_u + QK_STAGE_B, src_of(1), tid);
    CP_COMMIT();

    int buf = 0;
    for (int c = 0; c < ns; ++c) {
        CP_WAIT1();
        __syncthreads();

        int buf2 = buf + 2; if (buf2 >= 3) buf2 -= 3;
        if (c + 2 < ns) issue_stage_qk(base_u + (uint32_t)buf2 * QK_STAGE_B, src_of(c + 2), tid);
        CP_COMMIT();

        const uint32_t sbuf = base_u + (uint32_t)buf * QK_STAGE_B;
        const uint32_t Ab = sbuf, Bqs = sbuf + TILE_B, Bks = sbuf + 2 * TILE_B;

#pragma unroll
        for (int kk = 0; kk < 2; ++kk) {
            const uint32_t kb = (uint32_t)(kk * 32);
            uint32_t ah[2][4];
#pragma unroll
            for (int mt = 0; mt < 2; ++mt) {
                const uint32_t ra = a_base0 + (uint32_t)(mt * 16 * 80) + kb;
                ah[mt][0] = lds32(Ab + ra);
                ah[mt][1] = lds32(Ab + ra + 8 * 80);
                ah[mt][2] = lds32(Ab + ra + 16);
                ah[mt][3] = lds32(Ab + ra + 8 * 80 + 16);
            }
#pragma unroll
            for (int nt = 0; nt < 8; ++nt) {
                const uint32_t rb = b_base0 + (uint32_t)(nt * 8 * 80) + kb;
                const uint32_t q0 = lds32(Bqs + rb);
                const uint32_t q1 = lds32(Bqs + rb + 16);
                const uint32_t k0r = lds32(Bks + rb);
                const uint32_t k1r = lds32(Bks + rb + 16);
#pragma unroll
                for (int mt = 0; mt < 2; ++mt) {
                    mma16816h(accq[mt][nt], ah[mt], q0, q1);
                    mma16816h(acck[mt][nt], ah[mt], k0r, k1r);
                }
            }
        }
        if (++buf >= 3) buf -= 3;
    }

#pragma unroll
    for (int mt = 0; mt < 2; ++mt) {
#pragma unroll
        for (int nt = 0; nt < 8; ++nt) {
            const int col = warp_n + nt * 8 + 2 * qc;
            const int e   = e0 + col;
            const float qs0 = qsc[e] * WISCALE,     qs1 = qsc[e + 1] * WISCALE;
            const float qh0 = qsh[e],               qh1 = qsh[e + 1];
            const float ks0 = ksc[e] * WISCALE,     ks1 = ksc[e + 1] * WISCALE;
            const float kh0 = ksh[e],               kh1 = ksh[e + 1];
            const int row0 = warp_m + mt * 16 + qr;
            const size_t o0 = ((size_t)bt * 128 + row0) * Dd + e;
            const size_t o1 = ((size_t)bt * 128 + row0 + 8) * Dd + e;
            *(uint32_t*)(OutQ + o0) = packh2(accq[mt][nt][0] * qs0 + qh0, accq[mt][nt][1] * qs1 + qh1);
            *(uint32_t*)(OutQ + o1) = packh2(accq[mt][nt][2] * qs0 + qh0, accq[mt][nt][3] * qs1 + qh1);
            *(uint32_t*)(OutK + o0) = packh2(acck[mt][nt][0] * ks0 + kh0, acck[mt][nt][1] * ks1 + kh1);
            *(uint32_t*)(OutK + o1) = packh2(acck[mt][nt][2] * ks0 + kh0, acck[mt][nt][3] * ks1 + kh1);
        }
    }
}

// ---------- single-B GEMM (O projection) ----------
__global__ void __launch_bounds__(256, 2)
mma_gemm_one(const __half* __restrict__ A, const __half* __restrict__ B,
             const float* __restrict__ shift,
             float* __restrict__ OutF, __half* __restrict__ OutH)
{
    extern __shared__ __align__(16) char sm[];
    const uint32_t base_u = smem_u32(sm);

    const int tid = threadIdx.x;
    const int wid = tid >> 5;
    const int lane = tid & 31;
    const int qr = lane >> 2;
    const int qc = lane & 3;

    const int warp_m = (wid & 3) * 32;
    const int warp_n = (wid >> 2) * 64;

    const int e0 = blockIdx.x * 128;
    const int bt = blockIdx.y;
    const int ns = 16;

    auto src_of = [&](int c) -> StageSrc1 {
        const int k0 = c * 32;
        StageSrc1 r;
        r.a = A + (size_t)bt * 128 * Dd + k0;
        r.b = B + (size_t)e0 * Dd + k0;
        return r;
    };

    float acc[2][8][4];
#pragma unroll
    for (int i = 0; i < 2; ++i)
#pragma unroll
        for (int j = 0; j < 8; ++j)
#pragma unroll
            for (int q = 0; q < 4; ++q) acc[i][j][q] = 0.0f;

    issue_stage1(base_u, src_of(0), tid); CP_COMMIT();
    issue_stage1(base_u + ONE_STAGE_B, src_of(1), tid);
    CP_COMMIT();

    const uint32_t a_base0 = (uint32_t)((warp_m + qr) * 80 + qc * 4);
    const uint32_t b_base0 = (uint32_t)((warp_n + qr) * 80 + qc * 4);

    int buf = 0;
    for (int c = 0; c < ns; ++c) {
        CP_WAIT1();
        __syncthreads();

        int buf2 = buf + 2; if (buf2 >= 3) buf2 -= 3;
        if (c + 2 < ns) issue_stage1(base_u + (uint32_t)buf2 * ONE_STAGE_B, src_of(c + 2), tid);
        CP_COMMIT();

        const uint32_t sbuf = base_u + (uint32_t)buf * ONE_STAGE_B;
        const uint32_t Ab = sbuf, Bbs = sbuf + TILE_B;

#pragma unroll
        for (int kk = 0; kk < 2; ++kk) {
            const uint32_t kb = (uint32_t)(kk * 32);
            uint32_t ah[2][4];
#pragma unroll
            for (int mt = 0; mt < 2; ++mt) {
                const uint32_t ra = a_base0 + (uint32_t)(mt * 16 * 80) + kb;
                ah[mt][0] = lds32(Ab + ra);
                ah[mt][1] = lds32(Ab + ra + 8 * 80);
                ah[mt][2] = lds32(Ab + ra + 16);
                ah[mt][3] = lds32(Ab + ra + 8 * 80 + 16);
            }
#pragma unroll
            for (int nt = 0; nt < 8; ++nt) {
                const uint32_t rb = b_base0 + (uint32_t)(nt * 8 * 80) + kb;
                const uint32_t b0 = lds32(Bbs + rb);
                const uint32_t b1 = lds32(Bbs + rb + 16);
#pragma unroll
                for (int mt = 0; mt < 2; ++mt)
                    mma16816h(acc[mt][nt], ah[mt], b0, b1);
            }
        }
        if (++buf >= 3) buf -= 3;
    }

#pragma unroll
    for (int mt = 0; mt < 2; ++mt) {
#pragma unroll
        for (int nt = 0; nt < 8; ++nt) {
            const int col = warp_n + nt * 8 + 2 * qc;
            const int e   = e0 + col;
            const float h0 = shift[e], h1 = shift[e + 1];
            const int row0 = warp_m + mt * 16 + qr;
            const size_t o0 = ((size_t)bt * 128 + row0) * Dd + e;
            const size_t o1 = ((size_t)bt * 128 + row0 + 8) * Dd + e;
            const float v00 = acc[mt][nt][0] * WISCALE + h0;
            const float v01 = acc[mt][nt][1] * WISCALE + h1;
            const float v10 = acc[mt][nt][2] * WISCALE + h0;
            const float v11 = acc[mt][nt][3] * WISCALE + h1;
            if (OutF) {
                *(float2*)(OutF + o0) = make_float2(v00, v01);
                *(float2*)(OutF + o1) = make_float2(v10, v11);
            } else {
                *(uint32_t*)(OutH + o0) = packh2(v00, v01);
                *(uint32_t*)(OutH + o1) = packh2(v10, v11);
            }
        }
    }
}

// ======================= fp16 tensor-core attention (R12 proven) =======================
#define ATT_ROW 144
#define ATT_MAT (64 * ATT_ROW)        // 9216

__global__ void __launch_bounds__(128) attn_h16(
    const __half* __restrict__ Q, const __half* __restrict__ K,
    const __half* __restrict__ V, __half* __restrict__ O)
{
    __shared__ __align__(16) char sm[3 * ATT_MAT];
    const uint32_t s_u = smem_u32(sm);
    const uint32_t Qs = s_u, Ks = s_u + ATT_MAT, Vs = s_u + 2 * ATT_MAT;

    const int blk = blockIdx.x;
    const int h = blk & (KHh - 1);
    const int n = (blk >> 3) & (Nn - 1);
    const int b = blk >> 10;

    const int tid = threadIdx.x;
    const int wid = tid >> 5;
    const int lane = tid & 31;

    const size_t tstride = (size_t)Nn * Dd;
    const size_t base = ((size_t)b * Tt * Nn + n) * Dd + h * DHh;

#pragma unroll
    for (int i = 0; i < 4; ++i) {
        const int id = tid + 128 * i;
        const int r = id >> 3, c = id & 7;
        const size_t g = base + (size_t)r * tstride + c * 8;
        const uint32_t d = (uint32_t)(r * ATT_ROW + c * 16);
        *(uint4*)(sm + d)               = *(const uint4*)(Q + g);
        *(uint4*)(sm + ATT_MAT + d)     = *(const uint4*)(K + g);
        *(uint4*)(sm + 2 * ATT_MAT + d) = *(const uint4*)(V + g);
    }
    __syncthreads();

    const int m0 = wid * 16;

    // ---- S = Q @ K^T ----
    float s[8][4];
#pragma unroll
    for (int j = 0; j < 8; ++j)
#pragma unroll
        for (int q = 0; q < 4; ++q) s[j][q] = 0.0f;

#pragma unroll
    for (int ks = 0; ks < 4; ++ks) {
        const int k0 = ks * 16;
        uint32_t a[4];
        LDMX4(a, Qs + (uint32_t)((m0 + (lane & 15)) * ATT_ROW + 2 * k0 + (lane >> 4) * 16));
#pragma unroll
        for (int jp = 0; jp < 4; ++jp) {
            const int p0 = jp * 16;
            uint32_t kb[4];
            const int row = p0 + (lane & 7) + ((lane & 16) ? 8 : 0);
            const int colb = 2 * k0 + ((lane & 8) ? 16 : 0);
            LDMX4(kb, Ks + (uint32_t)(row * ATT_ROW + colb));
            mma16816h(s[2 * jp],     a, kb[0], kb[1]);
            mma16816h(s[2 * jp + 1], a, kb[2], kb[3]);
        }
    }

    // ---- softmax ----
    float mx0 = -1e30f, mx1 = -1e30f;
#pragma unroll
    for (int j = 0; j < 8; ++j) {
#pragma unroll
        for (int q = 0; q < 4; ++q) s[j][q] *= 0.125f;
        mx0 = fmaxf(mx0, fmaxf(s[j][0], s[j][1]));
        mx1 = fmaxf(mx1, fmaxf(s[j][2], s[j][3]));
    }
    mx0 = fmaxf(mx0, __shfl_xor_sync(0xffffffffu, mx0, 1));
    mx0 = fmaxf(mx0, __shfl_xor_sync(0xffffffffu, mx0, 2));
    mx1 = fmaxf(mx1, __shfl_xor_sync(0xffffffffu, mx1, 1));
    mx1 = fmaxf(mx1, __shfl_xor_sync(0xffffffffu, mx1, 2));

    float sum0 = 0.0f, sum1 = 0.0f;
#pragma unroll
    for (int j = 0; j < 8; ++j) {
        s[j][0] = __expf(s[j][0] - mx0);
        s[j][1] = __expf(s[j][1] - mx0);
        s[j][2] = __expf(s[j][2] - mx1);
        s[j][3] = __expf(s[j][3] - mx1);
        sum0 += s[j][0] + s[j][1];
        sum1 += s[j][2] + s[j][3];
    }
    sum0 += __shfl_xor_sync(0xffffffffu, sum0, 1);
    sum0 += __shfl_xor_sync(0xffffffffu, sum0, 2);
    sum1 += __shfl_xor_sync(0xffffffffu, sum1, 1);
    sum1 += __shfl_xor_sync(0xffffffffu, sum1, 2);
    const float inv0 = 1.0f / sum0;
    const float inv1 = 1.0f / sum1;

    // ---- O = P @ V ----
    float o[8][4];
#pragma unroll
    for (int j = 0; j < 8; ++j)
#pragma unroll
        for (int q = 0; q < 4; ++q) o[j][q] = 0.0f;

#pragma unroll
    for (int kk = 0; kk < 4; ++kk) {
        uint32_t a[4];
        a[0] = packh2(s[2 * kk][0] * inv0,     s[2 * kk][1] * inv0);
        a[1] = packh2(s[2 * kk][2] * inv1,     s[2 * kk][3] * inv1);
        a[2] = packh2(s[2 * kk + 1][0] * inv0, s[2 * kk + 1][1] * inv0);
        a[3] = packh2(s[2 * kk + 1][2] * inv1, s[2 * kk + 1][3] * inv1);
#pragma unroll
        for (int dp = 0; dp < 4; ++dp) {
            uint32_t vb[4];
            const int row = kk * 16 + (lane & 7) + ((lane & 8) ? 8 : 0);
            const int colb = dp * 32 + ((lane & 16) ? 16 : 0);
            LDMX4T(vb, Vs + (uint32_t)(row * ATT_ROW + colb));
            mma16816h(o[2 * dp],     a, vb[0], vb[1]);
            mma16816h(o[2 * dp + 1], a, vb[2], vb[3]);
        }
    }

    const int g0 = m0 + (lane >> 2);
#pragma unroll
    for (int dt = 0; dt < 8; ++dt) {
        const int col = dt * 8 + 2 * (lane & 3);
        *(uint32_t*)(O + base + (size_t)g0 * tstride + col)       = packh2(o[dt][0], o[dt][1]);
        *(uint32_t*)(O + base + (size_t)(g0 + 8) * tstride + col) = packh2(o[dt][2], o[dt][3]);
    }
}

// ======================= launch =======================
extern "C" void kernel_launch(void* const* d_in, const int* in_sizes, int n_in,
                              void* d_out, int out_size)
{
    const float* X     = (const float*)d_in[0];
    const float* Wq    = (const float*)d_in[1];
    const float* bq    = (const float*)d_in[2];
    const float* gq    = (const float*)d_in[3];
    const float* betaq = (const float*)d_in[4];
    const float* mq    = (const float*)d_in[5];
    const float* vq    = (const float*)d_in[6];
    const float* Wk    = (const float*)d_in[7];
    const float* bk    = (const float*)d_in[8];
    const float* gk    = (const float*)d_in[9];
    const float* betak = (const float*)d_in[10];
    const float* mk    = (const float*)d_in[11];
    const float* vk    = (const float*)d_in[12];
    const float* Wv    = (const float*)d_in[13];
    const float* bv    = (const float*)d_in[14];
    const float* Wo    = (const float*)d_in[15];
    const float* bo    = (const float*)d_in[16];
    float* out = (float*)d_out;

    float *pqsc, *pqsh, *pksc, *pksh;
    __half *pQh, *pKh, *pVh, *pXh, *pAOh, *pwqh, *pwkh, *pwvh, *pwoh;
    cudaGetSymbolAddress((void**)&pQh, g_Qh);
    cudaGetSymbolAddress((void**)&pKh, g_Kh);
    cudaGetSymbolAddress((void**)&pVh, g_Vh);
    cudaGetSymbolAddress((void**)&pXh, g_Xh);
    cudaGetSymbolAddress((void**)&pAOh, g_AOh);
    cudaGetSymbolAddress((void**)&pwqh, g_wqh);
    cudaGetSymbolAddress((void**)&pwkh, g_wkh);
    cudaGetSymbolAddress((void**)&pwvh, g_wvh);
    cudaGetSymbolAddress((void**)&pwoh, g_woh);
    cudaGetSymbolAddress((void**)&pqsc, g_qsc);
    cudaGetSymbolAddress((void**)&pqsh, g_qsh);
    cudaGetSymbolAddress((void**)&pksc, g_ksc);
    cudaGetSymbolAddress((void**)&pksh, g_ksh);

    cudaFuncSetAttribute(mma_gemm_qkv, cudaFuncAttributeMaxDynamicSharedMemorySize, SMEM_QK);
    cudaFuncSetAttribute(mma_gemm_one, cudaFuncAttributeMaxDynamicSharedMemorySize, SMEM_ONE);

    // prep (proven merged set: 4 launches)
    to_fp16<<<NELEM/4/256, 256>>>(X, pXh, NELEM);
    repack_conv2<<<(KSz*Dd*Dd + 255)/256, 256>>>(Wq, pwqh, Wk, pwkh);
    to_fp16_ws2<<<(Dd*Dd)/4/256, 256>>>(Wv, pwvh, Wo, pwoh, Dd*Dd);
    affine_k2<<<2, 256>>>(bq, gq, betaq, mq, vq, bk, gk, betak, mk, vk,
                          pqsc, pqsh, pksc, pksh);

    // merged Q+K conv GEMM (z=0) + V projection (z=1) -> fp16
    dim3 gridqkv(Dd/128, Bb*Tt, 2);
    mma_gemm_qkv<<<gridqkv, 256, SMEM_QK>>>(pXh, pwqh, pwkh, pwvh,
                                            pqsc, pqsh, pksc, pksh, bv,
                                            pQh, pKh, pVh);

    // tensor-core attention -> fp16 AO
    attn_h16<<<Bb*Nn*KHh, 128>>>(pQh, pKh, pVh, pAOh);

    // output projection -> fp32
    dim3 grid(Dd/128, Bb*Tt);
    mma_gemm_one<<<grid, 256, SMEM_ONE>>>(pAOh, pwoh, bo, out, nullptr);
}